// round 14
// baseline (speedup 1.0000x reference)
#include <cuda_runtime.h>
#include <cstdint>

typedef uint32_t u32;

constexpr int T_ = 2048;
constexpr int RS = 512;            // h*d floats between consecutive tokens
constexpr float EPSF = 1e-5f;

// smem: fp16 tiles, 128 rows x 64 cols, padded stride 72 elems (144B)
constexpr u32 TSTRIDE = 72;
constexpr u32 TILEB   = 128 * TSTRIDE * 2;   // 18432 B
constexpr u32 QHI  = 0;
constexpr u32 QLO  = QHI + TILEB;
constexpr u32 KVB0 = QLO + TILEB;            // buffer set: KH, VH (fp16, no lo tiles)
constexpr u32 KVSET = 2 * TILEB;             // 36864 B per set
constexpr u32 SMEM_BYTES = KVB0 + 2 * KVSET; // 110592 B

__device__ __forceinline__ u32 smem_u32(const void* p) {
    u32 a;
    asm("{ .reg .u64 t; cvta.to.shared.u64 t, %1; cvt.u32.u64 %0, t; }" : "=r"(a) : "l"(p));
    return a;
}
// pk2h(x,y): low 16 = fp16(x), high 16 = fp16(y)
__device__ __forceinline__ u32 pk2h(float x, float y) {
    u32 r; asm("cvt.rn.f16x2.f32 %0, %1, %2;" : "=r"(r) : "f"(y), "f"(x)); return r;
}
__device__ __forceinline__ float h2lo(u32 u) {
    float f; asm("{.reg .f16 a,b; mov.b32 {a,b}, %1; cvt.f32.f16 %0, a;}" : "=f"(f) : "r"(u));
    return f;
}
__device__ __forceinline__ float h2hi(u32 u) {
    float f; asm("{.reg .f16 a,b; mov.b32 {a,b}, %1; cvt.f32.f16 %0, b;}" : "=f"(f) : "r"(u));
    return f;
}

__device__ __forceinline__ void ldmx4(u32* r, u32 addr) {
    asm volatile("ldmatrix.sync.aligned.m8n8.x4.shared.b16 {%0,%1,%2,%3}, [%4];"
                 : "=r"(r[0]), "=r"(r[1]), "=r"(r[2]), "=r"(r[3]) : "r"(addr));
}
__device__ __forceinline__ void ldmx4t(u32* r, u32 addr) {
    asm volatile("ldmatrix.sync.aligned.m8n8.x4.trans.shared.b16 {%0,%1,%2,%3}, [%4];"
                 : "=r"(r[0]), "=r"(r[1]), "=r"(r[2]), "=r"(r[3]) : "r"(addr));
}
__device__ __forceinline__ void mma16816(float* c, const u32* a, u32 b0, u32 b1) {
    asm volatile(
        "mma.sync.aligned.m16n8k16.row.col.f32.f16.f16.f32 "
        "{%0,%1,%2,%3}, {%4,%5,%6,%7}, {%8,%9}, {%0,%1,%2,%3};"
        : "+f"(c[0]), "+f"(c[1]), "+f"(c[2]), "+f"(c[3])
        : "r"(a[0]), "r"(a[1]), "r"(a[2]), "r"(a[3]), "r"(b0), "r"(b1));
}

__global__ __launch_bounds__(256, 1)
void attn_pow2_mma(const float* __restrict__ Qg, const float* __restrict__ Kg,
                   const float* __restrict__ Vg, float* __restrict__ Og)
{
    extern __shared__ char smem[];
    const u32 sb = smem_u32(smem);

    const int tid  = (int)threadIdx.x;
    const int wid  = tid >> 5;
    const int lane = tid & 31;
    const int m0   = wid * 16;               // this warp's 16 query rows

    // LPT ordering: all 16 heaviest q-tiles launch first
    const int b  = (int)blockIdx.x;
    const int qt = 15 - (b >> 4);
    const int bh = b & 15;
    const size_t headoff = (size_t)(bh >> 3) * T_ * RS + (size_t)(bh & 7) * 64;
    const int qbase = qt * 128;
    const int nkt = qt + 1;

    // per-thread load coordinates (row n, feature col c4)
    const int ld_n  = tid >> 4;              // 0..15 (+16 per it)
    const int ld_c4 = (tid & 15) << 2;

    // ---- load Q tile once: fp16 hi/lo split into smem (Q stays ~exact) ----
    #pragma unroll
    for (int it = 0; it < 8; it++) {
        int n = ld_n + it * 16;
        float4 q = *(const float4*)(Qg + headoff + (size_t)(qbase + n) * RS + ld_c4);
        u32 h01 = pk2h(q.x, q.y), h23 = pk2h(q.z, q.w);
        u32 l01 = pk2h(q.x - h2lo(h01), q.y - h2hi(h01));
        u32 l23 = pk2h(q.z - h2lo(h23), q.w - h2hi(h23));
        u32 off = (u32)(n * TSTRIDE + ld_c4) * 2;
        *(uint2*)(smem + QHI + off) = make_uint2(h01, h23);
        *(uint2*)(smem + QLO + off) = make_uint2(l01, l23);
    }

    // ldmatrix per-lane address components
    const int a_r  = m0 + (lane & 7) + ((lane >> 3) & 1) * 8;  // A (Q): rows
    const int a_c8 = (lane >> 4) * 8;
    const int bk_r  = (lane & 7) + (lane >> 4) * 8;            // B (K): n rows
    const int bk_c8 = ((lane >> 3) & 1) * 8;
    const int vv_k  = (lane & 7) + ((lane >> 3) & 1) * 8;      // B (V, trans): k rows
    const int vv_c8 = (lane >> 4) * 8;

    float Y[8][4];
    #pragma unroll
    for (int j = 0; j < 8; j++)
        #pragma unroll
        for (int e = 0; e < 4; e++) Y[j][e] = 0.0f;
    float z0 = 0.0f, z1 = 0.0f;
    u32 ph[8][4], pl[8][4];

    float4 kreg[8], vreg[8];

    // ---- prologue: load + convert tile 0 into buffer 0 (fp16, hi only) ----
    #pragma unroll
    for (int it = 0; it < 8; it++) {
        int n = ld_n + it * 16;
        kreg[it] = *(const float4*)(Kg + headoff + (size_t)n * RS + ld_c4);
        vreg[it] = *(const float4*)(Vg + headoff + (size_t)n * RS + ld_c4);
    }
    {
        const u32 kh = KVB0, vh = kh + TILEB;
        #pragma unroll
        for (int it = 0; it < 8; it++) {
            int n = ld_n + it * 16;
            u32 off = (u32)(n * TSTRIDE + ld_c4) * 2;
            float4 k = kreg[it];
            *(uint2*)(smem + kh + off) = make_uint2(pk2h(k.x, k.y), pk2h(k.z, k.w));
            float4 v = vreg[it];
            *(uint2*)(smem + vh + off) = make_uint2(pk2h(v.x, v.y), pk2h(v.z, v.w));
        }
    }
    __syncthreads();

    for (int kt = 0; kt < nkt; kt++) {
        const int cur = kt & 1;
        const u32 kh = KVB0 + (u32)cur * KVSET;
        const u32 vh = kh + TILEB;

        const bool diag = (kt == nkt - 1);
        const int  jmax = diag ? wid : 7;   // triangular block skip on diag tile

        // ---- GEMM1: S = Qh·K^T + Ql·K^T  (K at fp16; 2 passes) ----
        float S[16][4];
        #pragma unroll
        for (int j = 0; j < 16; j++)
            #pragma unroll
            for (int e = 0; e < 4; e++) S[j][e] = 0.0f;

        #pragma unroll
        for (int ks = 0; ks < 4; ks++) {
            const int d0 = ks * 16;
            u32 qoff = (u32)(a_r * TSTRIDE + d0 + a_c8) * 2;
            u32 qh4[4], ql4[4];
            ldmx4(qh4, sb + QHI + qoff);
            ldmx4(ql4, sb + QLO + qoff);
            #pragma unroll
            for (int j2 = 0; j2 < 8; j2 += 2) {
                if (j2 > jmax) continue;           // warp-uniform skip
                const bool doB = (j2 + 1 <= jmax);
                u32 koffA = (u32)((j2 * 16 + bk_r) * TSTRIDE + d0 + bk_c8) * 2;
                u32 bhA[4];
                ldmx4(bhA, sb + kh + koffA);
                float* s0 = S[2 * j2];
                float* s1 = S[2 * j2 + 1];
                mma16816(s0, qh4, bhA[0], bhA[1]);
                mma16816(s1, qh4, bhA[2], bhA[3]);
                mma16816(s0, ql4, bhA[0], bhA[1]);
                mma16816(s1, ql4, bhA[2], bhA[3]);
                if (doB) {
                    u32 koffB = (u32)(((j2 + 1) * 16 + bk_r) * TSTRIDE + d0 + bk_c8) * 2;
                    u32 bhB[4];
                    ldmx4(bhB, sb + kh + koffB);
                    float* s2 = S[2 * j2 + 2];
                    float* s3 = S[2 * j2 + 3];
                    mma16816(s2, qh4, bhB[0], bhB[1]);
                    mma16816(s3, qh4, bhB[2], bhB[3]);
                    mma16816(s2, ql4, bhB[0], bhB[1]);
                    mma16816(s3, ql4, bhB[2], bhB[3]);
                }
            }
        }

        // ---- deep prefetch tile kt+1 (covered by GEMM2) ----
        const bool more = (kt + 1 < nkt);
        if (more) {
            const int kb = (kt + 1) * 128;
            #pragma unroll
            for (int it = 0; it < 8; it++) {
                int n = ld_n + it * 16;
                kreg[it] = *(const float4*)(Kg + headoff + (size_t)(kb + n) * RS + ld_c4);
                vreg[it] = *(const float4*)(Vg + headoff + (size_t)(kb + n) * RS + ld_c4);
            }
        }

        // ---- epilogue: P = S^2 (+causal mask), Z rowsum, fp16 hi/lo repack ----
        const int rlo = m0 + (lane >> 2);
        const int rhi = rlo + 8;
        #pragma unroll
        for (int t = 0; t < 8; t++) {
            if (t > jmax) continue;                // P == 0 above diagonal: skip
            #pragma unroll
            for (int h = 0; h < 2; h++) {
                const int j = 2 * t + h;
                float p0 = S[j][0] * S[j][0];
                float p1 = S[j][1] * S[j][1];
                float p2 = S[j][2] * S[j][2];
                float p3 = S[j][3] * S[j][3];
                if (diag) {
                    int c0 = 8 * j + 2 * (lane & 3);
                    if (c0     > rlo) p0 = 0.0f;
                    if (c0 + 1 > rlo) p1 = 0.0f;
                    if (c0     > rhi) p2 = 0.0f;
                    if (c0 + 1 > rhi) p3 = 0.0f;
                }
                z0 += p0 + p1;
                z1 += p2 + p3;
                u32 H0 = pk2h(p0, p1), H1 = pk2h(p2, p3);
                ph[t][2 * h]     = H0;
                ph[t][2 * h + 1] = H1;
                pl[t][2 * h]     = pk2h(p0 - h2lo(H0), p1 - h2hi(H0));
                pl[t][2 * h + 1] = pk2h(p2 - h2lo(H1), p3 - h2hi(H1));
            }
        }

        // ---- GEMM2: Y += Ph·V + Pl·V  (V at fp16; 2 passes) ----
        #pragma unroll
        for (int t = 0; t < 8; t++) {
            if (t > jmax) continue;                // P == 0 above diagonal: skip
            const int k0 = t * 16;
            #pragma unroll
            for (int v2 = 0; v2 < 4; v2 += 2) {
                u32 voffA = (u32)((k0 + vv_k) * TSTRIDE + v2 * 16 + vv_c8) * 2;
                u32 voffB = (u32)((k0 + vv_k) * TSTRIDE + (v2 + 1) * 16 + vv_c8) * 2;
                u32 vhA[4], vhB[4];
                ldmx4t(vhA, sb + vh + voffA);
                ldmx4t(vhB, sb + vh + voffB);
                float* y0 = Y[2 * v2];
                float* y1 = Y[2 * v2 + 1];
                float* y2 = Y[2 * v2 + 2];
                float* y3 = Y[2 * v2 + 3];
                mma16816(y0, ph[t], vhA[0], vhA[1]);
                mma16816(y1, ph[t], vhA[2], vhA[3]);
                mma16816(y2, ph[t], vhB[0], vhB[1]);
                mma16816(y3, ph[t], vhB[2], vhB[3]);
                mma16816(y0, pl[t], vhA[0], vhA[1]);
                mma16816(y1, pl[t], vhA[2], vhA[3]);
                mma16816(y2, pl[t], vhB[0], vhB[1]);
                mma16816(y3, pl[t], vhB[2], vhB[3]);
            }
        }

        // ---- convert prefetched tile kt+1 into the other buffer ----
        if (more) {
            const u32 nkh = KVB0 + (u32)(cur ^ 1) * KVSET;
            const u32 nvh = nkh + TILEB;
            #pragma unroll
            for (int it = 0; it < 8; it++) {
                int n = ld_n + it * 16;
                u32 off = (u32)(n * TSTRIDE + ld_c4) * 2;
                float4 k = kreg[it];
                *(uint2*)(smem + nkh + off) = make_uint2(pk2h(k.x, k.y), pk2h(k.z, k.w));
                float4 v = vreg[it];
                *(uint2*)(smem + nvh + off) = make_uint2(pk2h(v.x, v.y), pk2h(v.z, v.w));
            }
        }
        __syncthreads();
    }

    // ---- finalize: reduce Z across the 4 lanes sharing each row, write O = Y/Z ----
    z0 += __shfl_xor_sync(0xffffffffu, z0, 1);
    z0 += __shfl_xor_sync(0xffffffffu, z0, 2);
    z1 += __shfl_xor_sync(0xffffffffu, z1, 1);
    z1 += __shfl_xor_sync(0xffffffffu, z1, 2);
    const float inv0 = 1.0f / (z0 + EPSF);
    const float inv1 = 1.0f / (z1 + EPSF);

    const int rlo = m0 + (lane >> 2);
    float* orow0 = Og + headoff + (size_t)(qbase + rlo)     * RS;
    float* orow1 = Og + headoff + (size_t)(qbase + rlo + 8) * RS;
    #pragma unroll
    for (int j = 0; j < 8; j++) {
        int c0 = 8 * j + 2 * (lane & 3);
        *(float2*)(orow0 + c0) = make_float2(Y[j][0] * inv0, Y[j][1] * inv0);
        *(float2*)(orow1 + c0) = make_float2(Y[j][2] * inv1, Y[j][3] * inv1);
    }
}

extern "C" void kernel_launch(void* const* d_in, const int* in_sizes, int n_in,
                              void* d_out, int out_size)
{
    const float* Q = (const float*)d_in[0];
    const float* K = (const float*)d_in[1];
    const float* V = (const float*)d_in[2];
    float* O = (float*)d_out;

    cudaFuncSetAttribute(attn_pow2_mma,
                         cudaFuncAttributeMaxDynamicSharedMemorySize,
                         (int)SMEM_BYTES);

    dim3 grid(256);
    dim3 block(256);
    attn_pow2_mma<<<grid, block, SMEM_BYTES>>>(Q, K, V, O);
}

// round 15
// speedup vs baseline: 1.2067x; 1.2067x over previous
#include <cuda_runtime.h>
#include <cstdint>

typedef uint32_t u32;

constexpr int T_ = 2048;
constexpr int RS = 512;            // h*d floats between consecutive tokens
constexpr float EPSF = 1e-5f;

// smem: bf16 tiles, 128 rows x 64 cols, padded stride 72 elems (144B)
constexpr u32 TSTRIDE = 72;
constexpr u32 TILEB   = 128 * TSTRIDE * 2;   // 18432 B
constexpr u32 QHI  = 0;
constexpr u32 QLO  = QHI + TILEB;
constexpr u32 KVB0 = QLO + TILEB;            // buffer set 0: KHI,KLO,VHI,VLO
constexpr u32 KVSET = 4 * TILEB;             // 73728 B per set
constexpr u32 SMEM_BYTES = KVB0 + 2 * KVSET; // 184320 B

__device__ __forceinline__ u32 smem_u32(const void* p) {
    u32 a;
    asm("{ .reg .u64 t; cvta.to.shared.u64 t, %1; cvt.u32.u64 %0, t; }" : "=r"(a) : "l"(p));
    return a;
}
// pack2bf(x,y): low 16 = bf16(x), high 16 = bf16(y)
__device__ __forceinline__ u32 pack2bf(float x, float y) {
    u32 r; asm("cvt.rn.bf16x2.f32 %0, %1, %2;" : "=r"(r) : "f"(y), "f"(x)); return r;
}
__device__ __forceinline__ float bflo(u32 u) { return __uint_as_float(u << 16); }
__device__ __forceinline__ float bfhi(u32 u) { return __uint_as_float(u & 0xFFFF0000u); }

__device__ __forceinline__ void ldmx4(u32* r, u32 addr) {
    asm volatile("ldmatrix.sync.aligned.m8n8.x4.shared.b16 {%0,%1,%2,%3}, [%4];"
                 : "=r"(r[0]), "=r"(r[1]), "=r"(r[2]), "=r"(r[3]) : "r"(addr));
}
__device__ __forceinline__ void ldmx4t(u32* r, u32 addr) {
    asm volatile("ldmatrix.sync.aligned.m8n8.x4.trans.shared.b16 {%0,%1,%2,%3}, [%4];"
                 : "=r"(r[0]), "=r"(r[1]), "=r"(r[2]), "=r"(r[3]) : "r"(addr));
}
__device__ __forceinline__ void mma16816(float* c, const u32* a, u32 b0, u32 b1) {
    asm volatile(
        "mma.sync.aligned.m16n8k16.row.col.f32.bf16.bf16.f32 "
        "{%0,%1,%2,%3}, {%4,%5,%6,%7}, {%8,%9}, {%0,%1,%2,%3};"
        : "+f"(c[0]), "+f"(c[1]), "+f"(c[2]), "+f"(c[3])
        : "r"(a[0]), "r"(a[1]), "r"(a[2]), "r"(a[3]), "r"(b0), "r"(b1));
}

__global__ __launch_bounds__(256, 1)
void attn_pow2_mma(const float* __restrict__ Qg, const float* __restrict__ Kg,
                   const float* __restrict__ Vg, float* __restrict__ Og)
{
    extern __shared__ char smem[];
    const u32 sb = smem_u32(smem);

    const int tid  = (int)threadIdx.x;
    const int wid  = tid >> 5;
    const int lane = tid & 31;
    const int m0   = wid * 16;               // this warp's 16 query rows

    // LPT ordering: all 16 heaviest q-tiles launch first
    const int b  = (int)blockIdx.x;
    const int qt = 15 - (b >> 4);
    const int bh = b & 15;
    const size_t headoff = (size_t)(bh >> 3) * T_ * RS + (size_t)(bh & 7) * 64;
    const int qbase = qt * 128;
    const int nkt = qt + 1;

    // per-thread load coordinates (row n, feature col c4)
    const int ld_n  = tid >> 4;              // 0..15 (+16 per it)
    const int ld_c4 = (tid & 15) << 2;

    // ---- load Q tile once: bf16 hi/lo split into smem ----
    #pragma unroll
    for (int it = 0; it < 8; it++) {
        int n = ld_n + it * 16;
        float4 q = *(const float4*)(Qg + headoff + (size_t)(qbase + n) * RS + ld_c4);
        u32 h01 = pack2bf(q.x, q.y), h23 = pack2bf(q.z, q.w);
        u32 l01 = pack2bf(q.x - bflo(h01), q.y - bfhi(h01));
        u32 l23 = pack2bf(q.z - bflo(h23), q.w - bfhi(h23));
        u32 off = (u32)(n * TSTRIDE + ld_c4) * 2;
        *(uint2*)(smem + QHI + off) = make_uint2(h01, h23);
        *(uint2*)(smem + QLO + off) = make_uint2(l01, l23);
    }

    // ldmatrix per-lane address components
    const int a_r  = m0 + (lane & 7) + ((lane >> 3) & 1) * 8;  // A (Q): rows
    const int a_c8 = (lane >> 4) * 8;
    const int bk_r  = (lane & 7) + (lane >> 4) * 8;            // B (K): n rows
    const int bk_c8 = ((lane >> 3) & 1) * 8;
    const int vv_k  = (lane & 7) + ((lane >> 3) & 1) * 8;      // B (V, trans): k rows
    const int vv_c8 = (lane >> 4) * 8;

    float Y[8][4];
    #pragma unroll
    for (int j = 0; j < 8; j++)
        #pragma unroll
        for (int e = 0; e < 4; e++) Y[j][e] = 0.0f;
    float z0 = 0.0f, z1 = 0.0f;

    float4 kreg[8], vreg[8];

    // ---- prologue: load + convert tile 0 into buffer 0 ----
    #pragma unroll
    for (int it = 0; it < 8; it++) {
        int n = ld_n + it * 16;
        kreg[it] = *(const float4*)(Kg + headoff + (size_t)n * RS + ld_c4);
        vreg[it] = *(const float4*)(Vg + headoff + (size_t)n * RS + ld_c4);
    }
    {
        const u32 kh = KVB0, kl = kh + TILEB, vh = kl + TILEB, vl = vh + TILEB;
        #pragma unroll
        for (int it = 0; it < 8; it++) {
            int n = ld_n + it * 16;
            u32 off = (u32)(n * TSTRIDE + ld_c4) * 2;
            float4 k = kreg[it];
            u32 h01 = pack2bf(k.x, k.y), h23 = pack2bf(k.z, k.w);
            *(uint2*)(smem + kh + off) = make_uint2(h01, h23);
            *(uint2*)(smem + kl + off) = make_uint2(
                pack2bf(k.x - bflo(h01), k.y - bfhi(h01)),
                pack2bf(k.z - bflo(h23), k.w - bfhi(h23)));
            float4 v = vreg[it];
            u32 g01 = pack2bf(v.x, v.y), g23 = pack2bf(v.z, v.w);
            *(uint2*)(smem + vh + off) = make_uint2(g01, g23);
            *(uint2*)(smem + vl + off) = make_uint2(
                pack2bf(v.x - bflo(g01), v.y - bfhi(g01)),
                pack2bf(v.z - bflo(g23), v.w - bfhi(g23)));
        }
    }
    __syncthreads();

    for (int kt = 0; kt < nkt; kt++) {
        const int cur = kt & 1;
        const u32 kh = KVB0 + (u32)cur * KVSET;
        const u32 kl = kh + TILEB;
        const u32 vh = kl + TILEB;
        const u32 vl = vh + TILEB;

        const bool diag = (kt == nkt - 1);
        const int  jmax = diag ? wid : 7;   // triangular block skip on diag tile

        // ---- GEMM1: S = Qhi·Khi^T + Qhi·Klo^T + Qlo·Khi^T ----
        float S[16][4];
        #pragma unroll
        for (int j = 0; j < 16; j++)
            #pragma unroll
            for (int e = 0; e < 4; e++) S[j][e] = 0.0f;

        #pragma unroll
        for (int ks = 0; ks < 4; ks++) {
            const int d0 = ks * 16;
            u32 qoff = (u32)(a_r * TSTRIDE + d0 + a_c8) * 2;
            u32 qh4[4], ql4[4];
            ldmx4(qh4, sb + QHI + qoff);
            ldmx4(ql4, sb + QLO + qoff);
            #pragma unroll
            for (int j2 = 0; j2 < 8; j2 += 2) {
                if (j2 > jmax) continue;           // warp-uniform skip
                const bool doB = (j2 + 1 <= jmax);
                u32 koffA = (u32)((j2 * 16 + bk_r) * TSTRIDE + d0 + bk_c8) * 2;
                u32 bhA[4], blA[4];
                ldmx4(bhA, sb + kh + koffA);
                ldmx4(blA, sb + kl + koffA);
                float* s0 = S[2 * j2];
                float* s1 = S[2 * j2 + 1];
                mma16816(s0, qh4, bhA[0], bhA[1]);
                mma16816(s1, qh4, bhA[2], bhA[3]);
                mma16816(s0, qh4, blA[0], blA[1]);
                mma16816(s1, qh4, blA[2], blA[3]);
                mma16816(s0, ql4, bhA[0], bhA[1]);
                mma16816(s1, ql4, bhA[2], bhA[3]);
                if (doB) {
                    u32 koffB = (u32)(((j2 + 1) * 16 + bk_r) * TSTRIDE + d0 + bk_c8) * 2;
                    u32 bhB[4], blB[4];
                    ldmx4(bhB, sb + kh + koffB);
                    ldmx4(blB, sb + kl + koffB);
                    float* s2 = S[2 * j2 + 2];
                    float* s3 = S[2 * j2 + 3];
                    mma16816(s2, qh4, bhB[0], bhB[1]);
                    mma16816(s3, qh4, bhB[2], bhB[3]);
                    mma16816(s2, qh4, blB[0], blB[1]);
                    mma16816(s3, qh4, blB[2], blB[3]);
                    mma16816(s2, ql4, bhB[0], bhB[1]);
                    mma16816(s3, ql4, bhB[2], bhB[3]);
                }
            }
        }

        // ---- deep prefetch tile kt+1 (covered by fused epilogue+GEMM2) ----
        const bool more = (kt + 1 < nkt);
        if (more) {
            const int kb = (kt + 1) * 128;
            #pragma unroll
            for (int it = 0; it < 8; it++) {
                int n = ld_n + it * 16;
                kreg[it] = *(const float4*)(Kg + headoff + (size_t)(kb + n) * RS + ld_c4);
                vreg[it] = *(const float4*)(Vg + headoff + (size_t)(kb + n) * RS + ld_c4);
            }
        }

        // ---- fused epilogue + GEMM2 per k-chunk t: P lives 8 regs, transiently ----
        const int rlo = m0 + (lane >> 2);
        const int rhi = rlo + 8;
        #pragma unroll
        for (int t = 0; t < 8; t++) {
            if (t > jmax) continue;                // P == 0 above diagonal: skip
            u32 pht[4], plt[4];
            #pragma unroll
            for (int h = 0; h < 2; h++) {
                const int j = 2 * t + h;
                float p0 = S[j][0] * S[j][0];
                float p1 = S[j][1] * S[j][1];
                float p2 = S[j][2] * S[j][2];
                float p3 = S[j][3] * S[j][3];
                if (diag) {
                    int c0 = 8 * j + 2 * (lane & 3);
                    if (c0     > rlo) p0 = 0.0f;
                    if (c0 + 1 > rlo) p1 = 0.0f;
                    if (c0     > rhi) p2 = 0.0f;
                    if (c0 + 1 > rhi) p3 = 0.0f;
                }
                z0 += p0 + p1;
                z1 += p2 + p3;
                u32 H0 = pack2bf(p0, p1), H1 = pack2bf(p2, p3);
                pht[2 * h]     = H0;
                pht[2 * h + 1] = H1;
                plt[2 * h]     = pack2bf(p0 - bflo(H0), p1 - bfhi(H0));
                plt[2 * h + 1] = pack2bf(p2 - bflo(H1), p3 - bfhi(H1));
            }

            const int k0 = t * 16;
            #pragma unroll
            for (int v2 = 0; v2 < 4; v2 += 2) {
                u32 voffA = (u32)((k0 + vv_k) * TSTRIDE + v2 * 16 + vv_c8) * 2;
                u32 voffB = (u32)((k0 + vv_k) * TSTRIDE + (v2 + 1) * 16 + vv_c8) * 2;
                u32 vhA[4], vlA[4], vhB[4], vlB[4];
                ldmx4t(vhA, sb + vh + voffA);
                ldmx4t(vlA, sb + vl + voffA);
                ldmx4t(vhB, sb + vh + voffB);
                ldmx4t(vlB, sb + vl + voffB);
                float* y0 = Y[2 * v2];
                float* y1 = Y[2 * v2 + 1];
                float* y2 = Y[2 * v2 + 2];
                float* y3 = Y[2 * v2 + 3];
                mma16816(y0, pht, vhA[0], vhA[1]);
                mma16816(y1, pht, vhA[2], vhA[3]);
                mma16816(y2, pht, vhB[0], vhB[1]);
                mma16816(y3, pht, vhB[2], vhB[3]);
                mma16816(y0, pht, vlA[0], vlA[1]);
                mma16816(y1, pht, vlA[2], vlA[3]);
                mma16816(y2, pht, vlB[0], vlB[1]);
                mma16816(y3, pht, vlB[2], vlB[3]);
                mma16816(y0, plt, vhA[0], vhA[1]);
                mma16816(y1, plt, vhA[2], vhA[3]);
                mma16816(y2, plt, vhB[0], vhB[1]);
                mma16816(y3, plt, vhB[2], vhB[3]);
            }
        }

        // ---- convert prefetched tile kt+1 into the other buffer ----
        if (more) {
            const u32 nkh = KVB0 + (u32)(cur ^ 1) * KVSET;
            const u32 nkl = nkh + TILEB;
            const u32 nvh = nkl + TILEB;
            const u32 nvl = nvh + TILEB;
            #pragma unroll
            for (int it = 0; it < 8; it++) {
                int n = ld_n + it * 16;
                u32 off = (u32)(n * TSTRIDE + ld_c4) * 2;
                float4 k = kreg[it];
                u32 h01 = pack2bf(k.x, k.y), h23 = pack2bf(k.z, k.w);
                *(uint2*)(smem + nkh + off) = make_uint2(h01, h23);
                *(uint2*)(smem + nkl + off) = make_uint2(
                    pack2bf(k.x - bflo(h01), k.y - bfhi(h01)),
                    pack2bf(k.z - bflo(h23), k.w - bfhi(h23)));
                float4 v = vreg[it];
                u32 g01 = pack2bf(v.x, v.y), g23 = pack2bf(v.z, v.w);
                *(uint2*)(smem + nvh + off) = make_uint2(g01, g23);
                *(uint2*)(smem + nvl + off) = make_uint2(
                    pack2bf(v.x - bflo(g01), v.y - bfhi(g01)),
                    pack2bf(v.z - bflo(g23), v.w - bfhi(g23)));
            }
        }
        __syncthreads();
    }

    // ---- finalize: reduce Z across the 4 lanes sharing each row, write O = Y/Z ----
    z0 += __shfl_xor_sync(0xffffffffu, z0, 1);
    z0 += __shfl_xor_sync(0xffffffffu, z0, 2);
    z1 += __shfl_xor_sync(0xffffffffu, z1, 1);
    z1 += __shfl_xor_sync(0xffffffffu, z1, 2);
    const float inv0 = 1.0f / (z0 + EPSF);
    const float inv1 = 1.0f / (z1 + EPSF);

    const int rlo = m0 + (lane >> 2);
    float* orow0 = Og + headoff + (size_t)(qbase + rlo)     * RS;
    float* orow1 = Og + headoff + (size_t)(qbase + rlo + 8) * RS;
    #pragma unroll
    for (int j = 0; j < 8; j++) {
        int c0 = 8 * j + 2 * (lane & 3);
        *(float2*)(orow0 + c0) = make_float2(Y[j][0] * inv0, Y[j][1] * inv0);
        *(float2*)(orow1 + c0) = make_float2(Y[j][2] * inv1, Y[j][3] * inv1);
    }
}

extern "C" void kernel_launch(void* const* d_in, const int* in_sizes, int n_in,
                              void* d_out, int out_size)
{
    const float* Q = (const float*)d_in[0];
    const float* K = (const float*)d_in[1];
    const float* V = (const float*)d_in[2];
    float* O = (float*)d_out;

    cudaFuncSetAttribute(attn_pow2_mma,
                         cudaFuncAttributeMaxDynamicSharedMemorySize,
                         (int)SMEM_BYTES);

    dim3 grid(256);
    dim3 block(256);
    attn_pow2_mma<<<grid, block, SMEM_BYTES>>>(Q, K, V, O);
}

// round 16
// speedup vs baseline: 1.2616x; 1.0455x over previous
#include <cuda_runtime.h>
#include <cstdint>

typedef uint32_t u32;

constexpr int T_ = 2048;
constexpr int RS = 512;            // h*d floats between consecutive tokens
constexpr float EPSF = 1e-5f;

// smem: bf16 tiles, 128 rows x 64 cols, padded stride 72 elems (144B)
constexpr u32 TSTRIDE = 72;
constexpr u32 TILEB   = 128 * TSTRIDE * 2;   // 18432 B
constexpr u32 QHI  = 0;
constexpr u32 QLO  = QHI + TILEB;
constexpr u32 KVB0 = QLO + TILEB;            // buffer set 0: KHI,KLO,VHI,VLO
constexpr u32 KVSET = 4 * TILEB;             // 73728 B per set
constexpr u32 SMEM_BYTES = KVB0 + 2 * KVSET; // 184320 B

__device__ __forceinline__ u32 smem_u32(const void* p) {
    u32 a;
    asm("{ .reg .u64 t; cvta.to.shared.u64 t, %1; cvt.u32.u64 %0, t; }" : "=r"(a) : "l"(p));
    return a;
}
// pack2bf(x,y): low 16 = bf16(x), high 16 = bf16(y)
__device__ __forceinline__ u32 pack2bf(float x, float y) {
    u32 r; asm("cvt.rn.bf16x2.f32 %0, %1, %2;" : "=r"(r) : "f"(y), "f"(x)); return r;
}
__device__ __forceinline__ float bflo(u32 u) { return __uint_as_float(u << 16); }
__device__ __forceinline__ float bfhi(u32 u) { return __uint_as_float(u & 0xFFFF0000u); }

__device__ __forceinline__ void ldmx4(u32* r, u32 addr) {
    asm volatile("ldmatrix.sync.aligned.m8n8.x4.shared.b16 {%0,%1,%2,%3}, [%4];"
                 : "=r"(r[0]), "=r"(r[1]), "=r"(r[2]), "=r"(r[3]) : "r"(addr));
}
__device__ __forceinline__ void ldmx4t(u32* r, u32 addr) {
    asm volatile("ldmatrix.sync.aligned.m8n8.x4.trans.shared.b16 {%0,%1,%2,%3}, [%4];"
                 : "=r"(r[0]), "=r"(r[1]), "=r"(r[2]), "=r"(r[3]) : "r"(addr));
}
__device__ __forceinline__ void mma16816(float* c, const u32* a, u32 b0, u32 b1) {
    asm volatile(
        "mma.sync.aligned.m16n8k16.row.col.f32.bf16.bf16.f32 "
        "{%0,%1,%2,%3}, {%4,%5,%6,%7}, {%8,%9}, {%0,%1,%2,%3};"
        : "+f"(c[0]), "+f"(c[1]), "+f"(c[2]), "+f"(c[3])
        : "r"(a[0]), "r"(a[1]), "r"(a[2]), "r"(a[3]), "r"(b0), "r"(b1));
}

__global__ __launch_bounds__(256, 1)
void attn_pow2_mma(const float* __restrict__ Qg, const float* __restrict__ Kg,
                   const float* __restrict__ Vg, float* __restrict__ Og)
{
    extern __shared__ char smem[];
    const u32 sb = smem_u32(smem);

    const int tid  = (int)threadIdx.x;
    const int wid  = tid >> 5;
    const int lane = tid & 31;
    const int m0   = wid * 16;               // this warp's 16 query rows

    // LPT ordering: all 16 heaviest q-tiles launch first
    const int b  = (int)blockIdx.x;
    const int qt = 15 - (b >> 4);
    const int bh = b & 15;
    const size_t headoff = (size_t)(bh >> 3) * T_ * RS + (size_t)(bh & 7) * 64;
    const int qbase = qt * 128;
    const int nkt = qt + 1;

    // per-thread load coordinates (row n, feature col c4)
    const int ld_n  = tid >> 4;              // 0..15 (+16 per it)
    const int ld_c4 = (tid & 15) << 2;

    // ---- load Q tile once: bf16 hi/lo split into smem ----
    #pragma unroll
    for (int it = 0; it < 8; it++) {
        int n = ld_n + it * 16;
        float4 q = *(const float4*)(Qg + headoff + (size_t)(qbase + n) * RS + ld_c4);
        u32 h01 = pack2bf(q.x, q.y), h23 = pack2bf(q.z, q.w);
        u32 l01 = pack2bf(q.x - bflo(h01), q.y - bfhi(h01));
        u32 l23 = pack2bf(q.z - bflo(h23), q.w - bfhi(h23));
        u32 off = (u32)(n * TSTRIDE + ld_c4) * 2;
        *(uint2*)(smem + QHI + off) = make_uint2(h01, h23);
        *(uint2*)(smem + QLO + off) = make_uint2(l01, l23);
    }

    // ldmatrix per-lane address components
    const int a_r  = m0 + (lane & 7) + ((lane >> 3) & 1) * 8;  // A (Q): rows
    const int a_c8 = (lane >> 4) * 8;
    const int bk_r  = (lane & 7) + (lane >> 4) * 8;            // B (K): n rows
    const int bk_c8 = ((lane >> 3) & 1) * 8;
    const int vv_k  = (lane & 7) + ((lane >> 3) & 1) * 8;      // B (V, trans): k rows
    const int vv_c8 = (lane >> 4) * 8;

    float Y[8][4];
    #pragma unroll
    for (int j = 0; j < 8; j++)
        #pragma unroll
        for (int e = 0; e < 4; e++) Y[j][e] = 0.0f;
    float z0 = 0.0f, z1 = 0.0f;

    float4 kreg[8], vreg[8];

    // ---- prologue: load + convert tile 0 into buffer 0 ----
    #pragma unroll
    for (int it = 0; it < 8; it++) {
        int n = ld_n + it * 16;
        kreg[it] = *(const float4*)(Kg + headoff + (size_t)n * RS + ld_c4);
        vreg[it] = *(const float4*)(Vg + headoff + (size_t)n * RS + ld_c4);
    }
    {
        const u32 kh = KVB0, kl = kh + TILEB, vh = kl + TILEB, vl = vh + TILEB;
        #pragma unroll
        for (int it = 0; it < 8; it++) {
            int n = ld_n + it * 16;
            u32 off = (u32)(n * TSTRIDE + ld_c4) * 2;
            float4 k = kreg[it];
            u32 h01 = pack2bf(k.x, k.y), h23 = pack2bf(k.z, k.w);
            *(uint2*)(smem + kh + off) = make_uint2(h01, h23);
            *(uint2*)(smem + kl + off) = make_uint2(
                pack2bf(k.x - bflo(h01), k.y - bfhi(h01)),
                pack2bf(k.z - bflo(h23), k.w - bfhi(h23)));
            float4 v = vreg[it];
            u32 g01 = pack2bf(v.x, v.y), g23 = pack2bf(v.z, v.w);
            *(uint2*)(smem + vh + off) = make_uint2(g01, g23);
            *(uint2*)(smem + vl + off) = make_uint2(
                pack2bf(v.x - bflo(g01), v.y - bfhi(g01)),
                pack2bf(v.z - bflo(g23), v.w - bfhi(g23)));
        }
    }
    __syncthreads();

    // ---- cache Q fragments in registers for the whole kernel (ktile-invariant) ----
    u32 qfh[4][4], qfl[4][4];
    #pragma unroll
    for (int ks = 0; ks < 4; ks++) {
        u32 qoff = (u32)(a_r * TSTRIDE + ks * 16 + a_c8) * 2;
        ldmx4(qfh[ks], sb + QHI + qoff);
        ldmx4(qfl[ks], sb + QLO + qoff);
    }

    for (int kt = 0; kt < nkt; kt++) {
        const int cur = kt & 1;
        const u32 kh = KVB0 + (u32)cur * KVSET;
        const u32 kl = kh + TILEB;
        const u32 vh = kl + TILEB;
        const u32 vl = vh + TILEB;

        const bool diag = (kt == nkt - 1);
        const int  jmax = diag ? wid : 7;   // triangular block skip on diag tile
        const int  rlo  = m0 + (lane >> 2);
        const int  rhi  = rlo + 8;

        // ---- deep prefetch tile kt+1 (covered by the fused chunk loop) ----
        const bool more = (kt + 1 < nkt);
        if (more) {
            const int kb = (kt + 1) * 128;
            #pragma unroll
            for (int it = 0; it < 8; it++) {
                int n = ld_n + it * 16;
                kreg[it] = *(const float4*)(Kg + headoff + (size_t)(kb + n) * RS + ld_c4);
                vreg[it] = *(const float4*)(Vg + headoff + (size_t)(kb + n) * RS + ld_c4);
            }
        }

        // ---- fused per-32-col chunk: GEMM1 -> epilogue -> GEMM2 ----
        #pragma unroll
        for (int tp = 0; tp < 8; tp += 2) {
            if (tp > jmax) continue;               // warp-uniform skip
            const bool doB = (tp + 1 <= jmax);

            // GEMM1 chunk: S_c covers cols tp*16 .. tp*16+31
            float S_c[4][4];
            #pragma unroll
            for (int j = 0; j < 4; j++)
                #pragma unroll
                for (int e = 0; e < 4; e++) S_c[j][e] = 0.0f;

            #pragma unroll
            for (int ks = 0; ks < 4; ks++) {
                const int d0 = ks * 16;
                u32 koffA = (u32)((tp * 16 + bk_r) * TSTRIDE + d0 + bk_c8) * 2;
                u32 bhA[4], blA[4];
                ldmx4(bhA, sb + kh + koffA);
                ldmx4(blA, sb + kl + koffA);
                mma16816(S_c[0], qfh[ks], bhA[0], bhA[1]);
                mma16816(S_c[1], qfh[ks], bhA[2], bhA[3]);
                mma16816(S_c[0], qfh[ks], blA[0], blA[1]);
                mma16816(S_c[1], qfh[ks], blA[2], blA[3]);
                mma16816(S_c[0], qfl[ks], bhA[0], bhA[1]);
                mma16816(S_c[1], qfl[ks], bhA[2], bhA[3]);
                if (doB) {
                    u32 koffB = (u32)(((tp + 1) * 16 + bk_r) * TSTRIDE + d0 + bk_c8) * 2;
                    u32 bhB[4], blB[4];
                    ldmx4(bhB, sb + kh + koffB);
                    ldmx4(blB, sb + kl + koffB);
                    mma16816(S_c[2], qfh[ks], bhB[0], bhB[1]);
                    mma16816(S_c[3], qfh[ks], bhB[2], bhB[3]);
                    mma16816(S_c[2], qfh[ks], blB[0], blB[1]);
                    mma16816(S_c[3], qfh[ks], blB[2], blB[3]);
                    mma16816(S_c[2], qfl[ks], bhB[0], bhB[1]);
                    mma16816(S_c[3], qfl[ks], bhB[2], bhB[3]);
                }
            }

            // epilogue + GEMM2 for t = tp (and tp+1 if doB)
            #pragma unroll
            for (int u = 0; u < 2; u++) {
                if (u == 1 && !doB) continue;
                const int t = tp + u;
                u32 pht[4], plt[4];
                #pragma unroll
                for (int h = 0; h < 2; h++) {
                    float* Sj = S_c[2 * u + h];
                    const int j = 2 * t + h;
                    float p0 = Sj[0] * Sj[0];
                    float p1 = Sj[1] * Sj[1];
                    float p2 = Sj[2] * Sj[2];
                    float p3 = Sj[3] * Sj[3];
                    if (diag) {
                        int c0 = 8 * j + 2 * (lane & 3);
                        if (c0     > rlo) p0 = 0.0f;
                        if (c0 + 1 > rlo) p1 = 0.0f;
                        if (c0     > rhi) p2 = 0.0f;
                        if (c0 + 1 > rhi) p3 = 0.0f;
                    }
                    z0 += p0 + p1;
                    z1 += p2 + p3;
                    u32 H0 = pack2bf(p0, p1), H1 = pack2bf(p2, p3);
                    pht[2 * h]     = H0;
                    pht[2 * h + 1] = H1;
                    plt[2 * h]     = pack2bf(p0 - bflo(H0), p1 - bfhi(H0));
                    plt[2 * h + 1] = pack2bf(p2 - bflo(H1), p3 - bfhi(H1));
                }

                const int k0 = t * 16;
                #pragma unroll
                for (int v2 = 0; v2 < 4; v2 += 2) {
                    u32 voffA = (u32)((k0 + vv_k) * TSTRIDE + v2 * 16 + vv_c8) * 2;
                    u32 voffB = (u32)((k0 + vv_k) * TSTRIDE + (v2 + 1) * 16 + vv_c8) * 2;
                    u32 vhA[4], vlA[4], vhB[4], vlB[4];
                    ldmx4t(vhA, sb + vh + voffA);
                    ldmx4t(vlA, sb + vl + voffA);
                    ldmx4t(vhB, sb + vh + voffB);
                    ldmx4t(vlB, sb + vl + voffB);
                    float* y0 = Y[2 * v2];
                    float* y1 = Y[2 * v2 + 1];
                    float* y2 = Y[2 * v2 + 2];
                    float* y3 = Y[2 * v2 + 3];
                    mma16816(y0, pht, vhA[0], vhA[1]);
                    mma16816(y1, pht, vhA[2], vhA[3]);
                    mma16816(y2, pht, vhB[0], vhB[1]);
                    mma16816(y3, pht, vhB[2], vhB[3]);
                    mma16816(y0, pht, vlA[0], vlA[1]);
                    mma16816(y1, pht, vlA[2], vlA[3]);
                    mma16816(y2, pht, vlB[0], vlB[1]);
                    mma16816(y3, pht, vlB[2], vlB[3]);
                    mma16816(y0, plt, vhA[0], vhA[1]);
                    mma16816(y1, plt, vhA[2], vhA[3]);
                    mma16816(y2, plt, vhB[0], vhB[1]);
                    mma16816(y3, plt, vhB[2], vhB[3]);
                }
            }
        }

        // ---- convert prefetched tile kt+1 into the other buffer ----
        if (more) {
            const u32 nkh = KVB0 + (u32)(cur ^ 1) * KVSET;
            const u32 nkl = nkh + TILEB;
            const u32 nvh = nkl + TILEB;
            const u32 nvl = nvh + TILEB;
            #pragma unroll
            for (int it = 0; it < 8; it++) {
                int n = ld_n + it * 16;
                u32 off = (u32)(n * TSTRIDE + ld_c4) * 2;
                float4 k = kreg[it];
                u32 h01 = pack2bf(k.x, k.y), h23 = pack2bf(k.z, k.w);
                *(uint2*)(smem + nkh + off) = make_uint2(h01, h23);
                *(uint2*)(smem + nkl + off) = make_uint2(
                    pack2bf(k.x - bflo(h01), k.y - bfhi(h01)),
                    pack2bf(k.z - bflo(h23), k.w - bfhi(h23)));
                float4 v = vreg[it];
                u32 g01 = pack2bf(v.x, v.y), g23 = pack2bf(v.z, v.w);
                *(uint2*)(smem + nvh + off) = make_uint2(g01, g23);
                *(uint2*)(smem + nvl + off) = make_uint2(
                    pack2bf(v.x - bflo(g01), v.y - bfhi(g01)),
                    pack2bf(v.z - bflo(g23), v.w - bfhi(g23)));
            }
        }
        __syncthreads();
    }

    // ---- finalize: reduce Z across the 4 lanes sharing each row, write O = Y/Z ----
    z0 += __shfl_xor_sync(0xffffffffu, z0, 1);
    z0 += __shfl_xor_sync(0xffffffffu, z0, 2);
    z1 += __shfl_xor_sync(0xffffffffu, z1, 1);
    z1 += __shfl_xor_sync(0xffffffffu, z1, 2);
    const float inv0 = 1.0f / (z0 + EPSF);
    const float inv1 = 1.0f / (z1 + EPSF);

    const int rlo = m0 + (lane >> 2);
    float* orow0 = Og + headoff + (size_t)(qbase + rlo)     * RS;
    float* orow1 = Og + headoff + (size_t)(qbase + rlo + 8) * RS;
    #pragma unroll
    for (int j = 0; j < 8; j++) {
        int c0 = 8 * j + 2 * (lane & 3);
        *(float2*)(orow0 + c0) = make_float2(Y[j][0] * inv0, Y[j][1] * inv0);
        *(float2*)(orow1 + c0) = make_float2(Y[j][2] * inv1, Y[j][3] * inv1);
    }
}

extern "C" void kernel_launch(void* const* d_in, const int* in_sizes, int n_in,
                              void* d_out, int out_size)
{
    const float* Q = (const float*)d_in[0];
    const float* K = (const float*)d_in[1];
    const float* V = (const float*)d_in[2];
    float* O = (float*)d_out;

    cudaFuncSetAttribute(attn_pow2_mma,
                         cudaFuncAttributeMaxDynamicSharedMemorySize,
                         (int)SMEM_BYTES);

    dim3 grid(256);
    dim3 block(256);
    attn_pow2_mma<<<grid, block, SMEM_BYTES>>>(Q, K, V, O);
}

// round 17
// speedup vs baseline: 1.2647x; 1.0025x over previous
#include <cuda_runtime.h>
#include <cstdint>

typedef uint32_t u32;

constexpr int T_ = 2048;
constexpr int RS = 512;            // h*d floats between consecutive tokens
constexpr float EPSF = 1e-5f;

// smem: bf16 tiles, 128 rows x 64 cols, padded stride 72 elems (144B)
constexpr u32 TSTRIDE = 72;
constexpr u32 TILEB   = 128 * TSTRIDE * 2;   // 18432 B
constexpr u32 QHI  = 0;
constexpr u32 QLO  = QHI + TILEB;
constexpr u32 KVB0 = QLO + TILEB;            // buffer set 0: KHI,KLO,VHI,VLO
constexpr u32 KVSET = 4 * TILEB;             // 73728 B per set
constexpr u32 SMEM_BYTES = KVB0 + 2 * KVSET; // 184320 B

__device__ __forceinline__ u32 smem_u32(const void* p) {
    u32 a;
    asm("{ .reg .u64 t; cvta.to.shared.u64 t, %1; cvt.u32.u64 %0, t; }" : "=r"(a) : "l"(p));
    return a;
}
// pack2bf(x,y): low 16 = bf16(x), high 16 = bf16(y)
__device__ __forceinline__ u32 pack2bf(float x, float y) {
    u32 r; asm("cvt.rn.bf16x2.f32 %0, %1, %2;" : "=r"(r) : "f"(y), "f"(x)); return r;
}
__device__ __forceinline__ float bflo(u32 u) { return __uint_as_float(u << 16); }
__device__ __forceinline__ float bfhi(u32 u) { return __uint_as_float(u & 0xFFFF0000u); }

__device__ __forceinline__ void ldmx4(u32* r, u32 addr) {
    asm volatile("ldmatrix.sync.aligned.m8n8.x4.shared.b16 {%0,%1,%2,%3}, [%4];"
                 : "=r"(r[0]), "=r"(r[1]), "=r"(r[2]), "=r"(r[3]) : "r"(addr));
}
__device__ __forceinline__ void ldmx4t(u32* r, u32 addr) {
    asm volatile("ldmatrix.sync.aligned.m8n8.x4.trans.shared.b16 {%0,%1,%2,%3}, [%4];"
                 : "=r"(r[0]), "=r"(r[1]), "=r"(r[2]), "=r"(r[3]) : "r"(addr));
}
__device__ __forceinline__ void mma16816(float* c, const u32* a, u32 b0, u32 b1) {
    asm volatile(
        "mma.sync.aligned.m16n8k16.row.col.f32.bf16.bf16.f32 "
        "{%0,%1,%2,%3}, {%4,%5,%6,%7}, {%8,%9}, {%0,%1,%2,%3};"
        : "+f"(c[0]), "+f"(c[1]), "+f"(c[2]), "+f"(c[3])
        : "r"(a[0]), "r"(a[1]), "r"(a[2]), "r"(a[3]), "r"(b0), "r"(b1));
}

__global__ __launch_bounds__(256, 1)
void attn_pow2_mma(const float* __restrict__ Qg, const float* __restrict__ Kg,
                   const float* __restrict__ Vg, float* __restrict__ Og)
{
    extern __shared__ char smem[];
    const u32 sb = smem_u32(smem);

    const int tid  = (int)threadIdx.x;
    const int wid  = tid >> 5;
    const int lane = tid & 31;
    const int m0   = wid * 16;               // this warp's 16 query rows

    // LPT ordering: all 16 heaviest q-tiles launch first
    const int b  = (int)blockIdx.x;
    const int qt = 15 - (b >> 4);
    const int bh = b & 15;
    const size_t headoff = (size_t)(bh >> 3) * T_ * RS + (size_t)(bh & 7) * 64;
    const int qbase = qt * 128;
    const int nkt = qt + 1;

    // per-thread load coordinates (row n, feature col c4)
    const int ld_n  = tid >> 4;              // 0..15 (+16 per it)
    const int ld_c4 = (tid & 15) << 2;

    // ---- load Q tile once: bf16 hi/lo split into smem ----
    #pragma unroll
    for (int it = 0; it < 8; it++) {
        int n = ld_n + it * 16;
        float4 q = *(const float4*)(Qg + headoff + (size_t)(qbase + n) * RS + ld_c4);
        u32 h01 = pack2bf(q.x, q.y), h23 = pack2bf(q.z, q.w);
        u32 l01 = pack2bf(q.x - bflo(h01), q.y - bfhi(h01));
        u32 l23 = pack2bf(q.z - bflo(h23), q.w - bfhi(h23));
        u32 off = (u32)(n * TSTRIDE + ld_c4) * 2;
        *(uint2*)(smem + QHI + off) = make_uint2(h01, h23);
        *(uint2*)(smem + QLO + off) = make_uint2(l01, l23);
    }

    // ldmatrix per-lane address components
    const int a_r  = m0 + (lane & 7) + ((lane >> 3) & 1) * 8;  // A (Q): rows
    const int a_c8 = (lane >> 4) * 8;
    const int bk_r  = (lane & 7) + (lane >> 4) * 8;            // B (K): n rows
    const int bk_c8 = ((lane >> 3) & 1) * 8;
    const int vv_k  = (lane & 7) + ((lane >> 3) & 1) * 8;      // B (V, trans): k rows
    const int vv_c8 = (lane >> 4) * 8;

    float Y[8][4];
    #pragma unroll
    for (int j = 0; j < 8; j++)
        #pragma unroll
        for (int e = 0; e < 4; e++) Y[j][e] = 0.0f;
    float z0 = 0.0f, z1 = 0.0f;

    float4 kreg[8], vreg[8];

    // ---- prologue: load + convert tile 0 into buffer 0 ----
    #pragma unroll
    for (int it = 0; it < 8; it++) {
        int n = ld_n + it * 16;
        kreg[it] = *(const float4*)(Kg + headoff + (size_t)n * RS + ld_c4);
        vreg[it] = *(const float4*)(Vg + headoff + (size_t)n * RS + ld_c4);
    }
    {
        const u32 kh = KVB0, kl = kh + TILEB, vh = kl + TILEB, vl = vh + TILEB;
        #pragma unroll
        for (int it = 0; it < 8; it++) {
            int n = ld_n + it * 16;
            u32 off = (u32)(n * TSTRIDE + ld_c4) * 2;
            float4 k = kreg[it];
            u32 h01 = pack2bf(k.x, k.y), h23 = pack2bf(k.z, k.w);
            *(uint2*)(smem + kh + off) = make_uint2(h01, h23);
            *(uint2*)(smem + kl + off) = make_uint2(
                pack2bf(k.x - bflo(h01), k.y - bfhi(h01)),
                pack2bf(k.z - bflo(h23), k.w - bfhi(h23)));
            float4 v = vreg[it];
            u32 g01 = pack2bf(v.x, v.y), g23 = pack2bf(v.z, v.w);
            *(uint2*)(smem + vh + off) = make_uint2(g01, g23);
            *(uint2*)(smem + vl + off) = make_uint2(
                pack2bf(v.x - bflo(g01), v.y - bfhi(g01)),
                pack2bf(v.z - bflo(g23), v.w - bfhi(g23)));
        }
    }
    __syncthreads();

    // ---- cache Q fragments in registers for the whole kernel (ktile-invariant) ----
    u32 qfh[4][4], qfl[4][4];
    #pragma unroll
    for (int ks = 0; ks < 4; ks++) {
        u32 qoff = (u32)(a_r * TSTRIDE + ks * 16 + a_c8) * 2;
        ldmx4(qfh[ks], sb + QHI + qoff);
        ldmx4(qfl[ks], sb + QLO + qoff);
    }

    for (int kt = 0; kt < nkt; kt++) {
        const int cur = kt & 1;
        const u32 kh = KVB0 + (u32)cur * KVSET;
        const u32 kl = kh + TILEB;
        const u32 vh = kl + TILEB;
        const u32 vl = vh + TILEB;

        const bool diag = (kt == nkt - 1);
        const int  jmax = diag ? wid : 7;   // triangular block skip on diag tile
        const int  rlo  = m0 + (lane >> 2);
        const int  rhi  = rlo + 8;

        // ---- deep prefetch tile kt+1 (converted inside the chunk loop below) ----
        const bool more = (kt + 1 < nkt);
        const u32 nkh = KVB0 + (u32)(cur ^ 1) * KVSET;
        const u32 nkl = nkh + TILEB;
        const u32 nvh = nkl + TILEB;
        const u32 nvl = nvh + TILEB;
        if (more) {
            const int kb = (kt + 1) * 128;
            #pragma unroll
            for (int it = 0; it < 8; it++) {
                int n = ld_n + it * 16;
                kreg[it] = *(const float4*)(Kg + headoff + (size_t)(kb + n) * RS + ld_c4);
                vreg[it] = *(const float4*)(Vg + headoff + (size_t)(kb + n) * RS + ld_c4);
            }
        }

        // ---- fused per-32-col chunk: GEMM1 -> convert slice -> epilogue+GEMM2 ----
        // NOTE: diag-tile chunk pruning never skips converts: diag => last ktile
        // => more == false => no converts exist on pruned iterations.
        #pragma unroll
        for (int tp = 0; tp < 8; tp += 2) {
            if (tp > jmax) continue;               // warp-uniform skip
            const bool doB = (tp + 1 <= jmax);

            // GEMM1 chunk: S_c covers cols tp*16 .. tp*16+31
            float S_c[4][4];
            #pragma unroll
            for (int j = 0; j < 4; j++)
                #pragma unroll
                for (int e = 0; e < 4; e++) S_c[j][e] = 0.0f;

            #pragma unroll
            for (int ks = 0; ks < 4; ks++) {
                const int d0 = ks * 16;
                u32 koffA = (u32)((tp * 16 + bk_r) * TSTRIDE + d0 + bk_c8) * 2;
                u32 bhA[4], blA[4];
                ldmx4(bhA, sb + kh + koffA);
                ldmx4(blA, sb + kl + koffA);
                mma16816(S_c[0], qfh[ks], bhA[0], bhA[1]);
                mma16816(S_c[1], qfh[ks], bhA[2], bhA[3]);
                mma16816(S_c[0], qfh[ks], blA[0], blA[1]);
                mma16816(S_c[1], qfh[ks], blA[2], blA[3]);
                mma16816(S_c[0], qfl[ks], bhA[0], bhA[1]);
                mma16816(S_c[1], qfl[ks], bhA[2], bhA[3]);
                if (doB) {
                    u32 koffB = (u32)(((tp + 1) * 16 + bk_r) * TSTRIDE + d0 + bk_c8) * 2;
                    u32 bhB[4], blB[4];
                    ldmx4(bhB, sb + kh + koffB);
                    ldmx4(blB, sb + kl + koffB);
                    mma16816(S_c[2], qfh[ks], bhB[0], bhB[1]);
                    mma16816(S_c[3], qfh[ks], bhB[2], bhB[3]);
                    mma16816(S_c[2], qfh[ks], blB[0], blB[1]);
                    mma16816(S_c[3], qfh[ks], blB[2], blB[3]);
                    mma16816(S_c[2], qfl[ks], bhB[0], bhB[1]);
                    mma16816(S_c[3], qfl[ks], bhB[2], bhB[3]);
                }
            }

            // ---- interleaved convert: 2 of the 8 iterations of next tile ----
            if (more) {
                #pragma unroll
                for (int u = 0; u < 2; u++) {
                    const int it = tp + u;
                    int n = ld_n + it * 16;
                    u32 off = (u32)(n * TSTRIDE + ld_c4) * 2;
                    float4 k = kreg[it];
                    u32 h01 = pack2bf(k.x, k.y), h23 = pack2bf(k.z, k.w);
                    *(uint2*)(smem + nkh + off) = make_uint2(h01, h23);
                    *(uint2*)(smem + nkl + off) = make_uint2(
                        pack2bf(k.x - bflo(h01), k.y - bfhi(h01)),
                        pack2bf(k.z - bflo(h23), k.w - bfhi(h23)));
                    float4 v = vreg[it];
                    u32 g01 = pack2bf(v.x, v.y), g23 = pack2bf(v.z, v.w);
                    *(uint2*)(smem + nvh + off) = make_uint2(g01, g23);
                    *(uint2*)(smem + nvl + off) = make_uint2(
                        pack2bf(v.x - bflo(g01), v.y - bfhi(g01)),
                        pack2bf(v.z - bflo(g23), v.w - bfhi(g23)));
                }
            }

            // epilogue + GEMM2 for t = tp (and tp+1 if doB)
            #pragma unroll
            for (int u = 0; u < 2; u++) {
                if (u == 1 && !doB) continue;
                const int t = tp + u;
                u32 pht[4], plt[4];
                #pragma unroll
                for (int h = 0; h < 2; h++) {
                    float* Sj = S_c[2 * u + h];
                    const int j = 2 * t + h;
                    float p0 = Sj[0] * Sj[0];
                    float p1 = Sj[1] * Sj[1];
                    float p2 = Sj[2] * Sj[2];
                    float p3 = Sj[3] * Sj[3];
                    if (diag) {
                        int c0 = 8 * j + 2 * (lane & 3);
                        if (c0     > rlo) p0 = 0.0f;
                        if (c0 + 1 > rlo) p1 = 0.0f;
                        if (c0     > rhi) p2 = 0.0f;
                        if (c0 + 1 > rhi) p3 = 0.0f;
                    }
                    z0 += p0 + p1;
                    z1 += p2 + p3;
                    u32 H0 = pack2bf(p0, p1), H1 = pack2bf(p2, p3);
                    pht[2 * h]     = H0;
                    pht[2 * h + 1] = H1;
                    plt[2 * h]     = pack2bf(p0 - bflo(H0), p1 - bfhi(H0));
                    plt[2 * h + 1] = pack2bf(p2 - bflo(H1), p3 - bfhi(H1));
                }

                const int k0 = t * 16;
                #pragma unroll
                for (int v2 = 0; v2 < 4; v2 += 2) {
                    u32 voffA = (u32)((k0 + vv_k) * TSTRIDE + v2 * 16 + vv_c8) * 2;
                    u32 voffB = (u32)((k0 + vv_k) * TSTRIDE + (v2 + 1) * 16 + vv_c8) * 2;
                    u32 vhA[4], vlA[4], vhB[4], vlB[4];
                    ldmx4t(vhA, sb + vh + voffA);
                    ldmx4t(vlA, sb + vl + voffA);
                    ldmx4t(vhB, sb + vh + voffB);
                    ldmx4t(vlB, sb + vl + voffB);
                    float* y0 = Y[2 * v2];
                    float* y1 = Y[2 * v2 + 1];
                    float* y2 = Y[2 * v2 + 2];
                    float* y3 = Y[2 * v2 + 3];
                    mma16816(y0, pht, vhA[0], vhA[1]);
                    mma16816(y1, pht, vhA[2], vhA[3]);
                    mma16816(y2, pht, vhB[0], vhB[1]);
                    mma16816(y3, pht, vhB[2], vhB[3]);
                    mma16816(y0, pht, vlA[0], vlA[1]);
                    mma16816(y1, pht, vlA[2], vlA[3]);
                    mma16816(y2, pht, vlB[0], vlB[1]);
                    mma16816(y3, pht, vlB[2], vlB[3]);
                    mma16816(y0, plt, vhA[0], vhA[1]);
                    mma16816(y1, plt, vhA[2], vhA[3]);
                    mma16816(y2, plt, vhB[0], vhB[1]);
                    mma16816(y3, plt, vhB[2], vhB[3]);
                }
            }
        }

        __syncthreads();
    }

    // ---- finalize: reduce Z across the 4 lanes sharing each row, write O = Y/Z ----
    z0 += __shfl_xor_sync(0xffffffffu, z0, 1);
    z0 += __shfl_xor_sync(0xffffffffu, z0, 2);
    z1 += __shfl_xor_sync(0xffffffffu, z1, 1);
    z1 += __shfl_xor_sync(0xffffffffu, z1, 2);
    const float inv0 = 1.0f / (z0 + EPSF);
    const float inv1 = 1.0f / (z1 + EPSF);

    const int rlo = m0 + (lane >> 2);
    float* orow0 = Og + headoff + (size_t)(qbase + rlo)     * RS;
    float* orow1 = Og + headoff + (size_t)(qbase + rlo + 8) * RS;
    #pragma unroll
    for (int j = 0; j < 8; j++) {
        int c0 = 8 * j + 2 * (lane & 3);
        *(float2*)(orow0 + c0) = make_float2(Y[j][0] * inv0, Y[j][1] * inv0);
        *(float2*)(orow1 + c0) = make_float2(Y[j][2] * inv1, Y[j][3] * inv1);
    }
}

extern "C" void kernel_launch(void* const* d_in, const int* in_sizes, int n_in,
                              void* d_out, int out_size)
{
    const float* Q = (const float*)d_in[0];
    const float* K = (const float*)d_in[1];
    const float* V = (const float*)d_in[2];
    float* O = (float*)d_out;

    cudaFuncSetAttribute(attn_pow2_mma,
                         cudaFuncAttributeMaxDynamicSharedMemorySize,
                         (int)SMEM_BYTES);

    dim3 grid(256);
    dim3 block(256);
    attn_pow2_mma<<<grid, block, SMEM_BYTES>>>(Q, K, V, O);
}